// round 6
// baseline (speedup 1.0000x reference)
#include <cuda_runtime.h>
#include <cuda_fp16.h>
#include <math.h>
#include <stdint.h>

// Problem constants
#define B_SZ   256
#define IN_SZ  512
#define OUT_SZ 512
#define R_SZ   4
#define H_SZ   4608             // (IN+OUT)*R + OUT
#define G4_SZ  (4*H_SZ)         // 18432  (gate columns)
#define NX_SZ  (G4_SZ + OUT_SZ) // 18944  (gates + x@W0^T columns) = 148*128
#define K_TOT  (IN_SZ + H_SZ)   // 5120

// GEMM tile config (fp16 mma.sync m16n8k16)
#define BM 128
#define BN 128
#define BK 32                   // 32 halves of k per stage
#define BKP 40                  // padded row (80 B: 16B-aligned, conflict-free)
#define NTHREADS 256

// Scratch (no cudaMalloc allowed)
__device__ float g_gates[B_SZ * NX_SZ];   // 19.4 MB

// ---------------------------------------------------------------------------
__device__ __forceinline__ void mma_f16(float c[4],
                                        uint32_t a0, uint32_t a1, uint32_t a2, uint32_t a3,
                                        uint32_t b0, uint32_t b1) {
    asm volatile(
        "mma.sync.aligned.m16n8k16.row.col.f32.f16.f16.f32 "
        "{%0,%1,%2,%3}, {%4,%5,%6,%7}, {%8,%9}, {%0,%1,%2,%3};"
        : "+f"(c[0]), "+f"(c[1]), "+f"(c[2]), "+f"(c[3])
        : "r"(a0), "r"(a1), "r"(a2), "r"(a3), "r"(b0), "r"(b1));
}

#define LDSM_X4(r0, r1, r2, r3, a) \
    asm volatile("ldmatrix.sync.aligned.m8n8.x4.shared.b16 {%0,%1,%2,%3}, [%4];" \
        : "=r"(r0), "=r"(r1), "=r"(r2), "=r"(r3) : "r"(a))

__device__ __forceinline__ uint32_t h2u(__half2 h) {
    return *reinterpret_cast<uint32_t*>(&h);
}
__device__ __forceinline__ uint32_t smem_u32(const void* p) {
    uint32_t a;
    asm("{ .reg .u64 t; cvta.to.shared.u64 t, %1; cvt.u32.u64 %0, t; }" : "=r"(a) : "l"(p));
    return a;
}

// ---------------------------------------------------------------------------
// Kernel 1: C[m, n'] row-major [256 x 18944] into g_gates:
//   n' < G4:  [x|h0] @ [Wih|Whh]^T + (bih+bhh)
//   n' >= G4: x @ W0^T   (K loop only over k<512)
// fp16 mma.sync + ldmatrix, 128x128x32 stages, 8 warps, double-buffered smem.
// ---------------------------------------------------------------------------
__global__ __launch_bounds__(NTHREADS, 2)
void gates_gemm(const float* __restrict__ x,  const float* __restrict__ h0,
                const float* __restrict__ Wih, const float* __restrict__ Whh,
                const float* __restrict__ bih, const float* __restrict__ bhh,
                const float* __restrict__ W0)
{
    __shared__ __align__(16) __half As[2][BM][BKP];
    __shared__ __align__(16) __half Bs[2][BN][BKP];

    const int tid = threadIdx.x;
    const int bm  = blockIdx.y * BM;
    const int bn  = blockIdx.x * BN;
    const bool isW0 = (bn >= G4_SZ);                      // block-uniform
    const int NIT = isW0 ? (IN_SZ / BK) : (K_TOT / BK);   // 16 or 160

    const int warp = tid >> 5;
    const int lane = tid & 31;
    const int wm0 = (warp & 3) * 32;   // warp m-strip
    const int wn0 = (warp >> 2) * 64;  // warp n-strip
    const int q   = lane & 3;
    const int t8  = lane >> 2;

    float acc[2][8][4];
#pragma unroll
    for (int mi = 0; mi < 2; mi++)
#pragma unroll
        for (int ni = 0; ni < 8; ni++)
#pragma unroll
            for (int e = 0; e < 4; e++) acc[mi][ni][e] = 0.f;

    // ldmatrix base addresses (buffer 0)
    uint32_t aA[2], aB[4];
#pragma unroll
    for (int mi = 0; mi < 2; mi++)
        aA[mi] = smem_u32(&As[0][wm0 + mi * 16 + (lane & 15)][(lane >> 4) * 8]);
#pragma unroll
    for (int j = 0; j < 4; j++)
        aB[j] = smem_u32(&Bs[0][wn0 + j * 16 + ((lane & 16) >> 1) + (lane & 7)][lane & 8]);
    const uint32_t ABUF = sizeof(As[0]);   // 10240 bytes per buffer (same for Bs)

    // staging registers
    float4 ra[4], rb[4];

    auto ldg_tile = [&](int t) {
        const int k0 = t * BK;
        const float* baseA; long sA;
        if (k0 < IN_SZ) { baseA = x + (long)bm * IN_SZ + k0; sA = IN_SZ; }
        else            { baseA = h0 + (long)bm * H_SZ + (k0 - IN_SZ); sA = H_SZ; }
#pragma unroll
        for (int j = 0; j < 4; j++) {
            int ch = j * 256 + tid, row = ch >> 3, c = ch & 7;
            ra[j] = *reinterpret_cast<const float4*>(baseA + (long)row * sA + c * 4);
        }
        const float* baseB; long sB;
        if (isW0)            { baseB = W0 + (long)(bn - G4_SZ) * IN_SZ + k0; sB = IN_SZ; }
        else if (k0 < IN_SZ) { baseB = Wih + (long)bn * IN_SZ + k0; sB = IN_SZ; }
        else                 { baseB = Whh + (long)bn * H_SZ + (k0 - IN_SZ); sB = H_SZ; }
#pragma unroll
        for (int j = 0; j < 4; j++) {
            int ch = j * 256 + tid, row = ch >> 3, c = ch & 7;
            rb[j] = *reinterpret_cast<const float4*>(baseB + (long)row * sB + c * 4);
        }
    };

    auto sts_tile = [&](int buf) {
#pragma unroll
        for (int j = 0; j < 4; j++) {
            int ch = j * 256 + tid, row = ch >> 3, c = ch & 7;
            __half2 ha = __floats2half2_rn(ra[j].x, ra[j].y);
            __half2 hb = __floats2half2_rn(ra[j].z, ra[j].w);
            *reinterpret_cast<uint2*>(&As[buf][row][c * 4]) = make_uint2(h2u(ha), h2u(hb));
        }
#pragma unroll
        for (int j = 0; j < 4; j++) {
            int ch = j * 256 + tid, row = ch >> 3, c = ch & 7;
            __half2 ha = __floats2half2_rn(rb[j].x, rb[j].y);
            __half2 hb = __floats2half2_rn(rb[j].z, rb[j].w);
            *reinterpret_cast<uint2*>(&Bs[buf][row][c * 4]) = make_uint2(h2u(ha), h2u(hb));
        }
    };

    auto compute = [&](int buf) {
        const uint32_t boff = buf * ABUF;
#pragma unroll
        for (int ks = 0; ks < 2; ks++) {
            const uint32_t koff = boff + ks * 32;   // 16 halves = 32 bytes
            uint32_t a0[4], a1[4];
            LDSM_X4(a0[0], a0[1], a0[2], a0[3], aA[0] + koff);
            LDSM_X4(a1[0], a1[1], a1[2], a1[3], aA[1] + koff);
#pragma unroll
            for (int j = 0; j < 4; j++) {
                uint32_t b[4];
                LDSM_X4(b[0], b[1], b[2], b[3], aB[j] + koff);
                mma_f16(acc[0][2*j],   a0[0], a0[1], a0[2], a0[3], b[0], b[1]);
                mma_f16(acc[1][2*j],   a1[0], a1[1], a1[2], a1[3], b[0], b[1]);
                mma_f16(acc[0][2*j+1], a0[0], a0[1], a0[2], a0[3], b[2], b[3]);
                mma_f16(acc[1][2*j+1], a1[0], a1[1], a1[2], a1[3], b[2], b[3]);
            }
        }
    };

    // prologue
    ldg_tile(0);
    sts_tile(0);
    __syncthreads();

    int buf = 0;
    for (int t = 1; t < NIT; t++) {
        ldg_tile(t);
        compute(buf);
        sts_tile(buf ^ 1);
        __syncthreads();
        buf ^= 1;
    }
    compute(buf);

    // epilogue: + bias for gate columns, store fp32
#pragma unroll
    for (int ni = 0; ni < 8; ni++) {
        const int n2 = bn + wn0 + ni * 8 + q * 2;
        float bv0 = 0.f, bv1 = 0.f;
        if (!isW0) {
            bv0 = bih[n2] + bhh[n2];
            bv1 = bih[n2 + 1] + bhh[n2 + 1];
        }
#pragma unroll
        for (int mi = 0; mi < 2; mi++) {
            const int row = bm + wm0 + mi * 16 + t8;
            float2 v0 = make_float2(acc[mi][ni][0] + bv0, acc[mi][ni][1] + bv1);
            float2 v1 = make_float2(acc[mi][ni][2] + bv0, acc[mi][ni][3] + bv1);
            *reinterpret_cast<float2*>(g_gates + (long)row * NX_SZ + n2)       = v0;
            *reinterpret_cast<float2*>(g_gates + (long)(row + 8) * NX_SZ + n2) = v1;
        }
    }
}

// ---------------------------------------------------------------------------
// Kernel 2 (fused tail): per-batch block computes LSTM elementwise, z, and y.
// grid = 256 (one block per b), 512 threads.
// ---------------------------------------------------------------------------
__device__ __forceinline__ float sigm(float v) { return 1.0f / (1.0f + expf(-v)); }

__global__ __launch_bounds__(512)
void tail_fused(const float* __restrict__ x, const float* __restrict__ c0,
                const float* __restrict__ bias0,
                float* __restrict__ y, float* __restrict__ h_out,
                float* __restrict__ c_out)
{
    __shared__ float sh[H_SZ];      // h_new for this batch
    __shared__ float sx[IN_SZ];
    __shared__ float sz[R_SZ];

    const int b   = blockIdx.x;
    const int tid = threadIdx.x;
    const float* gb = g_gates + (long)b * NX_SZ;

    sx[tid] = x[b * IN_SZ + tid];

    // Phase 1: LSTM elementwise (9 elements per thread, coalesced)
#pragma unroll
    for (int j = 0; j < H_SZ / 512; j++) {
        int hh = j * 512 + tid;
        float gi = sigm(gb[hh]);
        float gf = sigm(gb[H_SZ + hh]);
        float gg = tanhf(gb[2 * H_SZ + hh]);
        float go = sigm(gb[3 * H_SZ + hh]);
        float c  = gf * c0[(long)b * H_SZ + hh] + gi * gg;
        float hn = go * tanhf(c);
        c_out[(long)b * H_SZ + hh] = c;
        h_out[(long)b * H_SZ + hh] = hn;
        sh[hh] = hn;
    }
    __syncthreads();

    // Phase 2: z[r] = dot(dw2[r,:], x)   (warps 0..3)
    const int wid  = tid >> 5;
    const int lane = tid & 31;
    if (wid < 4) {
        const float* dw2 = sh + OUT_SZ * R_SZ + wid * IN_SZ;
        float s = 0.f;
#pragma unroll
        for (int i = lane; i < IN_SZ; i += 32) s = fmaf(dw2[i], sx[i], s);
#pragma unroll
        for (int off = 16; off; off >>= 1) s += __shfl_xor_sync(0xffffffffu, s, off);
        if (lane == 0) sz[wid] = s;
    }
    __syncthreads();

    // Phase 3: y[o] = xw0 + bias0 + db + sum_r dw1[o,r]*z[r]
    const int o = tid;
    float v = gb[G4_SZ + o] + bias0[o] + sh[OUT_SZ * R_SZ + IN_SZ * R_SZ + o];
    float4 w1 = *reinterpret_cast<const float4*>(sh + o * R_SZ);
    v = fmaf(w1.x, sz[0], v);
    v = fmaf(w1.y, sz[1], v);
    v = fmaf(w1.z, sz[2], v);
    v = fmaf(w1.w, sz[3], v);
    y[b * OUT_SZ + o] = v;
}

// ---------------------------------------------------------------------------
extern "C" void kernel_launch(void* const* d_in, const int* in_sizes, int n_in,
                              void* d_out, int out_size)
{
    const float* x     = (const float*)d_in[0];
    const float* h0    = (const float*)d_in[1];
    const float* c0    = (const float*)d_in[2];
    const float* Wih   = (const float*)d_in[3];
    const float* Whh   = (const float*)d_in[4];
    const float* bih   = (const float*)d_in[5];
    const float* bhh   = (const float*)d_in[6];
    const float* W0    = (const float*)d_in[7];
    const float* bias0 = (const float*)d_in[8];

    float* y     = (float*)d_out;                 // [B, OUT]
    float* h_out = y + B_SZ * OUT_SZ;             // [B, H]
    float* c_out = h_out + B_SZ * H_SZ;           // [B, H]

    dim3 ggrid(NX_SZ / BN, B_SZ / BM);            // (148, 2) = 296 blocks
    gates_gemm<<<ggrid, NTHREADS>>>(x, h0, Wih, Whh, bih, bhh, W0);

    tail_fused<<<B_SZ, 512>>>(x, c0, bias0, y, h_out, c_out);
}

// round 7
// speedup vs baseline: 1.1003x; 1.1003x over previous
#include <cuda_runtime.h>
#include <cuda_fp16.h>
#include <math.h>
#include <stdint.h>

// Problem constants
#define B_SZ   256
#define IN_SZ  512
#define OUT_SZ 512
#define R_SZ   4
#define H_SZ   4608             // (IN+OUT)*R + OUT
#define G4_SZ  (4*H_SZ)         // 18432  (gate columns)
#define NX_SZ  (G4_SZ + OUT_SZ) // 18944  (gates + x@W0^T columns) = 148*128
#define K_TOT  (IN_SZ + H_SZ)   // 5120

// GEMM tile config (fp16 mma.sync m16n8k16)
#define BM 128
#define BN 128
#define BK 32                   // 32 halves of k per stage
#define BKP 40                  // padded row (80 B: 16B-aligned, conflict-free)
#define NBUF 4                  // 4-deep smem ring
#define NTHREADS 256
#define ATILE (BM * BKP)        // halves per A buffer
#define BTILE (BN * BKP)        // halves per B buffer
#define SMEM_BYTES (NBUF * (ATILE + BTILE) * 2)   // 81920

// Scratch (no cudaMalloc allowed)
__device__ float g_gates[B_SZ * NX_SZ];   // 19.4 MB
__device__ float g_z[B_SZ * R_SZ];

// ---------------------------------------------------------------------------
__device__ __forceinline__ void mma_f16(float c[4],
                                        uint32_t a0, uint32_t a1, uint32_t a2, uint32_t a3,
                                        uint32_t b0, uint32_t b1) {
    asm volatile(
        "mma.sync.aligned.m16n8k16.row.col.f32.f16.f16.f32 "
        "{%0,%1,%2,%3}, {%4,%5,%6,%7}, {%8,%9}, {%0,%1,%2,%3};"
        : "+f"(c[0]), "+f"(c[1]), "+f"(c[2]), "+f"(c[3])
        : "r"(a0), "r"(a1), "r"(a2), "r"(a3), "r"(b0), "r"(b1));
}

__device__ __forceinline__ uint32_t h2u(__half2 h) {
    return *reinterpret_cast<uint32_t*>(&h);
}

// ---------------------------------------------------------------------------
// Kernel 1: C[m, n'] row-major [256 x 18944] into g_gates:
//   n' < G4:  [x|h0] @ [Wih|Whh]^T + (bih+bhh)
//   n' >= G4: x @ W0^T   (K loop only over k<512)
// fp16 mma.sync, 128x128x32 stages, 8 warps of 32x64,
// 4-deep smem ring, __syncthreads every 2 stages.
// ---------------------------------------------------------------------------
__global__ __launch_bounds__(NTHREADS, 2)
void gates_gemm(const float* __restrict__ x,  const float* __restrict__ h0,
                const float* __restrict__ Wih, const float* __restrict__ Whh,
                const float* __restrict__ bih, const float* __restrict__ bhh,
                const float* __restrict__ W0)
{
    extern __shared__ __align__(16) __half dynsmem[];
    __half (*As)[BM][BKP] = reinterpret_cast<__half (*)[BM][BKP]>(dynsmem);
    __half (*Bs)[BN][BKP] = reinterpret_cast<__half (*)[BN][BKP]>(dynsmem + NBUF * ATILE);

    const int tid = threadIdx.x;
    const int bm  = blockIdx.y * BM;
    const int bn  = blockIdx.x * BN;
    const bool isW0 = (bn >= G4_SZ);                      // block-uniform
    const int NIT = isW0 ? (IN_SZ / BK) : (K_TOT / BK);   // 16 or 160

    const int warp = tid >> 5;
    const int lane = tid & 31;
    const int wm0 = (warp & 3) * 32;   // warp m-strip
    const int wn0 = (warp >> 2) * 64;  // warp n-strip
    const int q   = lane & 3;          // k quad
    const int t8  = lane >> 2;         // row/col within 8

    float acc[2][8][4];
#pragma unroll
    for (int mi = 0; mi < 2; mi++)
#pragma unroll
        for (int ni = 0; ni < 8; ni++)
#pragma unroll
            for (int e = 0; e < 4; e++) acc[mi][ni][e] = 0.f;

    // staging registers
    float4 ra[4], rb[4];

    auto ldg_tile = [&](int t) {
        const int k0 = t * BK;
        const float* baseA; long sA;
        if (k0 < IN_SZ) { baseA = x + (long)bm * IN_SZ + k0; sA = IN_SZ; }
        else            { baseA = h0 + (long)bm * H_SZ + (k0 - IN_SZ); sA = H_SZ; }
#pragma unroll
        for (int j = 0; j < 4; j++) {
            int ch = j * 256 + tid, row = ch >> 3, c = ch & 7;
            ra[j] = *reinterpret_cast<const float4*>(baseA + (long)row * sA + c * 4);
        }
        const float* baseB; long sB;
        if (isW0)            { baseB = W0 + (long)(bn - G4_SZ) * IN_SZ + k0; sB = IN_SZ; }
        else if (k0 < IN_SZ) { baseB = Wih + (long)bn * IN_SZ + k0; sB = IN_SZ; }
        else                 { baseB = Whh + (long)bn * H_SZ + (k0 - IN_SZ); sB = H_SZ; }
#pragma unroll
        for (int j = 0; j < 4; j++) {
            int ch = j * 256 + tid, row = ch >> 3, c = ch & 7;
            rb[j] = *reinterpret_cast<const float4*>(baseB + (long)row * sB + c * 4);
        }
    };

    auto sts_tile = [&](int buf) {
#pragma unroll
        for (int j = 0; j < 4; j++) {
            int ch = j * 256 + tid, row = ch >> 3, c = ch & 7;
            __half2 ha = __floats2half2_rn(ra[j].x, ra[j].y);
            __half2 hb = __floats2half2_rn(ra[j].z, ra[j].w);
            *reinterpret_cast<uint2*>(&As[buf][row][c * 4]) = make_uint2(h2u(ha), h2u(hb));
        }
#pragma unroll
        for (int j = 0; j < 4; j++) {
            int ch = j * 256 + tid, row = ch >> 3, c = ch & 7;
            __half2 ha = __floats2half2_rn(rb[j].x, rb[j].y);
            __half2 hb = __floats2half2_rn(rb[j].z, rb[j].w);
            *reinterpret_cast<uint2*>(&Bs[buf][row][c * 4]) = make_uint2(h2u(ha), h2u(hb));
        }
    };

    auto compute = [&](int buf) {
#pragma unroll
        for (int ks = 0; ks < 2; ks++) {
            const int kb = ks * 16;
            uint32_t a[2][4];
#pragma unroll
            for (int mi = 0; mi < 2; mi++) {
                int r0 = wm0 + mi * 16 + t8;
                a[mi][0] = h2u(*reinterpret_cast<const __half2*>(&As[buf][r0    ][kb + 2 * q    ]));
                a[mi][1] = h2u(*reinterpret_cast<const __half2*>(&As[buf][r0 + 8][kb + 2 * q    ]));
                a[mi][2] = h2u(*reinterpret_cast<const __half2*>(&As[buf][r0    ][kb + 2 * q + 8]));
                a[mi][3] = h2u(*reinterpret_cast<const __half2*>(&As[buf][r0 + 8][kb + 2 * q + 8]));
            }
#pragma unroll
            for (int ni = 0; ni < 8; ni++) {
                int nc = wn0 + ni * 8 + t8;
                uint32_t b0 = h2u(*reinterpret_cast<const __half2*>(&Bs[buf][nc][kb + 2 * q    ]));
                uint32_t b1 = h2u(*reinterpret_cast<const __half2*>(&Bs[buf][nc][kb + 2 * q + 8]));
                mma_f16(acc[0][ni], a[0][0], a[0][1], a[0][2], a[0][3], b0, b1);
                mma_f16(acc[1][ni], a[1][0], a[1][1], a[1][2], a[1][3], b0, b1);
            }
        }
    };

    // prologue: fill buffers 0 and 1
    ldg_tile(0);
    sts_tile(0);
    ldg_tile(1);
    sts_tile(1);
    __syncthreads();

    for (int t = 0; t < NIT; t++) {
        if (t + 2 < NIT) ldg_tile(t + 2);     // prefetch 2 stages ahead
        compute(t & (NBUF - 1));
        if (t + 2 < NIT) sts_tile((t + 2) & (NBUF - 1));
        if (t & 1) __syncthreads();           // barrier every 2 stages
    }

    // epilogue: + bias for gate columns, store fp32
#pragma unroll
    for (int ni = 0; ni < 8; ni++) {
        const int n2 = bn + wn0 + ni * 8 + q * 2;
        float bv0 = 0.f, bv1 = 0.f;
        if (!isW0) {
            bv0 = bih[n2] + bhh[n2];
            bv1 = bih[n2 + 1] + bhh[n2 + 1];
        }
#pragma unroll
        for (int mi = 0; mi < 2; mi++) {
            const int row = bm + wm0 + mi * 16 + t8;
            float2 v0 = make_float2(acc[mi][ni][0] + bv0, acc[mi][ni][1] + bv1);
            float2 v1 = make_float2(acc[mi][ni][2] + bv0, acc[mi][ni][3] + bv1);
            *reinterpret_cast<float2*>(g_gates + (long)row * NX_SZ + n2)       = v0;
            *reinterpret_cast<float2*>(g_gates + (long)(row + 8) * NX_SZ + n2) = v1;
        }
    }
}

// ---------------------------------------------------------------------------
// Kernel 2: LSTM elementwise -> h_new, c_new
// ---------------------------------------------------------------------------
__device__ __forceinline__ float sigm(float v) { return 1.0f / (1.0f + expf(-v)); }

__global__ __launch_bounds__(256)
void lstm_eltwise(const float* __restrict__ c0,
                  float* __restrict__ h_out, float* __restrict__ c_out)
{
    int idx = blockIdx.x * blockDim.x + threadIdx.x;   // over B*H
    if (idx >= B_SZ * H_SZ) return;
    int b = idx / H_SZ;
    int h = idx - b * H_SZ;
    const float* gb = g_gates + (long)b * NX_SZ;
    float gi = sigm(gb[h]);
    float gf = sigm(gb[H_SZ + h]);
    float gg = tanhf(gb[2 * H_SZ + h]);
    float go = sigm(gb[3 * H_SZ + h]);
    float c  = gf * c0[idx] + gi * gg;
    float hn = go * tanhf(c);
    c_out[idx] = c;
    h_out[idx] = hn;
}

// ---------------------------------------------------------------------------
// Kernel 3: z[b,r] = dot(dw2[b,r,:], x[b,:])
// ---------------------------------------------------------------------------
__global__ __launch_bounds__(128)
void z_kernel(const float* __restrict__ hn, const float* __restrict__ x)
{
    int b    = blockIdx.x;
    int r    = threadIdx.x >> 5;
    int lane = threadIdx.x & 31;
    const float* dw2 = hn + (long)b * H_SZ + OUT_SZ * R_SZ + r * IN_SZ;
    const float* xb  = x + b * IN_SZ;
    float s = 0.f;
    for (int i = lane; i < IN_SZ; i += 32) s = fmaf(dw2[i], xb[i], s);
#pragma unroll
    for (int off = 16; off; off >>= 1) s += __shfl_xor_sync(0xffffffffu, s, off);
    if (lane == 0) g_z[b * R_SZ + r] = s;
}

// ---------------------------------------------------------------------------
// Kernel 4: y[b,o] = xw0[b,o] + bias0[o] + db[b,o] + sum_r dw1[b,o,r]*z[b,r]
// ---------------------------------------------------------------------------
__global__ __launch_bounds__(256)
void y_final(const float* __restrict__ hn, const float* __restrict__ bias0,
             float* __restrict__ y)
{
    int idx = blockIdx.x * blockDim.x + threadIdx.x;   // over B*OUT
    if (idx >= B_SZ * OUT_SZ) return;
    int b = idx >> 9;
    int o = idx & 511;
    const float* h = hn + (long)b * H_SZ;
    float v = g_gates[(long)b * NX_SZ + G4_SZ + o] + bias0[o]
            + h[OUT_SZ * R_SZ + IN_SZ * R_SZ + o];
    float4 w1 = *reinterpret_cast<const float4*>(h + o * R_SZ);
    const float* zb = g_z + b * R_SZ;
    v = fmaf(w1.x, zb[0], v);
    v = fmaf(w1.y, zb[1], v);
    v = fmaf(w1.z, zb[2], v);
    v = fmaf(w1.w, zb[3], v);
    y[idx] = v;
}

// ---------------------------------------------------------------------------
extern "C" void kernel_launch(void* const* d_in, const int* in_sizes, int n_in,
                              void* d_out, int out_size)
{
    const float* x     = (const float*)d_in[0];
    const float* h0    = (const float*)d_in[1];
    const float* c0    = (const float*)d_in[2];
    const float* Wih   = (const float*)d_in[3];
    const float* Whh   = (const float*)d_in[4];
    const float* bih   = (const float*)d_in[5];
    const float* bhh   = (const float*)d_in[6];
    const float* W0    = (const float*)d_in[7];
    const float* bias0 = (const float*)d_in[8];

    float* y     = (float*)d_out;                 // [B, OUT]
    float* h_out = y + B_SZ * OUT_SZ;             // [B, H]
    float* c_out = h_out + B_SZ * H_SZ;           // [B, H]

    cudaFuncSetAttribute(gates_gemm, cudaFuncAttributeMaxDynamicSharedMemorySize, SMEM_BYTES);

    dim3 ggrid(NX_SZ / BN, B_SZ / BM);            // (148, 2) = 296 blocks
    gates_gemm<<<ggrid, NTHREADS, SMEM_BYTES>>>(x, h0, Wih, Whh, bih, bhh, W0);

    int n = B_SZ * H_SZ;
    lstm_eltwise<<<(n + 255) / 256, 256>>>(c0, h_out, c_out);

    z_kernel<<<B_SZ, 128>>>(h_out, x);

    int m = B_SZ * OUT_SZ;
    y_final<<<(m + 255) / 256, 256>>>(h_out, bias0, y);
}